// round 1
// baseline (speedup 1.0000x reference)
#include <cuda_runtime.h>
#include <cuda_fp16.h>
#include <mma.h>

using namespace nvcuda;

#define Bc 4
#define Sc 1024
#define Ec 512
#define Hc 8
#define Dc 64
#define BHc 32

// ---- scratch (device globals; no runtime allocation allowed) ----
__device__ __half g_Qh[BHc * Sc * Dc];            // 4 MB  [bh][s][d]
__device__ __half g_Kh[BHc * Sc * Dc];            // 4 MB  [bh][t][d]
__device__ __half g_Ch[BHc * Sc * Dc];            // 4 MB  [bh][t][d]
__device__ __half g_Th[Bc * Sc * Ec];             // 4 MB  [b][t][e]
__device__ float  g_Sem[(size_t)BHc * Sc * Sc];   // 128 MB [bh][i][t]
__device__ float  g_Gram[(size_t)BHc * Sc * Sc];  // 128 MB [bh][i][t]
__device__ __half g_W[(size_t)BHc * Sc * Sc];     // 64 MB  [bh][i][t]

__device__ __forceinline__ float fast_tanh(float x) {
    float y;
    asm("tanh.approx.f32 %0, %1;" : "=f"(y) : "f"(x));
    return y;
}

// ---- K0: convert + head-split to fp16 ----
__global__ void convert_kernel(const float* __restrict__ src,
                               const float* __restrict__ tgt) {
    int idx = blockIdx.x * blockDim.x + threadIdx.x;
    if (idx >= Bc * Sc * Ec) return;
    int e = idx % Ec;
    int s = (idx / Ec) % Sc;
    int b = idx / (Ec * Sc);
    int h = e / Dc, d = e % Dc;
    float sv = src[idx], tv = tgt[idx];
    int qidx = ((b * Hc + h) * Sc + s) * Dc + d;
    g_Qh[qidx] = __float2half(sv);
    g_Kh[qidx] = __float2half(tv);
    g_Th[idx]  = __float2half(tv);
}

// ---- K1: sequential recurrence c_t = tanh(carry*pe); carry = k_t*c_t ----
// elementwise in (b,h,d): 32 blocks x 64 threads
__global__ void recurrence_kernel(const float* __restrict__ tgt,
                                  const float* __restrict__ enc) {
    int bh = blockIdx.x;
    int d = threadIdx.x;
    int b = bh / Hc, h = bh % Hc;
    float pe = enc[h * Dc + d];
    const float* kp = tgt + (size_t)b * Sc * Ec + h * Dc + d;  // stride Ec per t
    __half* cp = g_Ch + (size_t)bh * Sc * Dc + d;              // stride Dc per t
    float c = kp[0];
#pragma unroll 4
    for (int t = 0; t < Sc; t++) {
        float kt = kp[(size_t)t * Ec];
        float ct = fast_tanh(c * pe);
        cp[(size_t)t * Dc] = __float2half(ct);
        c = kt * ct;
    }
}

// ---- K2: dual GEMM  Sem[i,t]=Q.Kt  Gram[i,t]=Q.Ct  (per bh, M=N=1024, K=64) ----
// block: 128 threads (4 warps), 64x64 output tile
__global__ void qk_qc_gemm() {
    int bh = blockIdx.z;
    int i0 = blockIdx.x * 64;
    int j0 = blockIdx.y * 64;
    __shared__ __half As[64 * 64];
    __shared__ __half Ks[64 * 64];
    __shared__ __half Cs[64 * 64];
    int tid = threadIdx.x;

    const int4* qsrc = (const int4*)(g_Qh + (size_t)bh * Sc * Dc + (size_t)i0 * Dc);
    const int4* ksrc = (const int4*)(g_Kh + (size_t)bh * Sc * Dc + (size_t)j0 * Dc);
    const int4* csrc = (const int4*)(g_Ch + (size_t)bh * Sc * Dc + (size_t)j0 * Dc);
    int4* ad = (int4*)As;
    int4* kd = (int4*)Ks;
    int4* cd = (int4*)Cs;
#pragma unroll
    for (int l = 0; l < 4; l++) {
        int o = tid + l * 128;
        ad[o] = qsrc[o];
        kd[o] = ksrc[o];
        cd[o] = csrc[o];
    }
    __syncthreads();

    int warp = tid >> 5;
    int r0 = warp * 16;
    wmma::fragment<wmma::accumulator, 16, 16, 16, float> accS[4], accG[4];
#pragma unroll
    for (int n = 0; n < 4; n++) {
        wmma::fill_fragment(accS[n], 0.0f);
        wmma::fill_fragment(accG[n], 0.0f);
    }
#pragma unroll
    for (int kk = 0; kk < 4; kk++) {
        wmma::fragment<wmma::matrix_a, 16, 16, 16, __half, wmma::row_major> a;
        wmma::load_matrix_sync(a, As + r0 * 64 + kk * 16, 64);
#pragma unroll
        for (int n = 0; n < 4; n++) {
            wmma::fragment<wmma::matrix_b, 16, 16, 16, __half, wmma::col_major> bk, bc;
            wmma::load_matrix_sync(bk, Ks + n * 16 * 64 + kk * 16, 64);
            wmma::load_matrix_sync(bc, Cs + n * 16 * 64 + kk * 16, 64);
            wmma::mma_sync(accS[n], a, bk, accS[n]);
            wmma::mma_sync(accG[n], a, bc, accG[n]);
        }
    }
    size_t base = (size_t)bh * Sc * Sc + (size_t)(i0 + r0) * Sc + j0;
#pragma unroll
    for (int n = 0; n < 4; n++) {
        wmma::store_matrix_sync(g_Sem + base + n * 16, accS[n], Sc, wmma::mem_row_major);
        wmma::store_matrix_sync(g_Gram + base + n * 16, accG[n], Sc, wmma::mem_row_major);
    }
}

// ---- K3: per-row: grammar softmax, combine, final softmax -> W (fp16) ----
// one block per row (bh*S rows), 256 threads, 4 elements/thread
__global__ void softmax_kernel(const float* __restrict__ ap,
                               const float* __restrict__ bp,
                               const float* __restrict__ gp) {
    __shared__ float red[256];
    int tid = threadIdx.x;
    size_t row = blockIdx.x;
    const float* gr = g_Gram + row * (size_t)Sc;
    const float* sr = g_Sem + row * (size_t)Sc;
    __half* wr = g_W + row * (size_t)Sc;

    float alpha = ap[0] * 0.01f;  // fold 1/100
    float beta = bp[0];
    float ginv = 1.0f / gp[0];

    float g[4], s[4];
#pragma unroll
    for (int l = 0; l < 4; l++) {
        int t = tid + l * 256;
        g[l] = gr[t] * 0.125f;  // 1/sqrt(D)
        s[l] = sr[t] * alpha;
    }
    // grammar softmax: max
    float m = fmaxf(fmaxf(g[0], g[1]), fmaxf(g[2], g[3]));
    red[tid] = m;
    __syncthreads();
    for (int st = 128; st > 0; st >>= 1) {
        if (tid < st) red[tid] = fmaxf(red[tid], red[tid + st]);
        __syncthreads();
    }
    m = red[0];
    __syncthreads();
    // grammar softmax: exp+sum
    float sum = 0.0f;
#pragma unroll
    for (int l = 0; l < 4; l++) {
        g[l] = __expf(g[l] - m);
        sum += g[l];
    }
    red[tid] = sum;
    __syncthreads();
    for (int st = 128; st > 0; st >>= 1) {
        if (tid < st) red[tid] += red[tid + st];
        __syncthreads();
    }
    float wgt = beta * ginv / red[0];  // grammar weight folded with 1/sum and 1/gamma
    __syncthreads();

    // combined logits
    float lg[4];
#pragma unroll
    for (int l = 0; l < 4; l++) lg[l] = s[l] * ginv + g[l] * wgt;

    // final softmax: max
    float m2 = fmaxf(fmaxf(lg[0], lg[1]), fmaxf(lg[2], lg[3]));
    red[tid] = m2;
    __syncthreads();
    for (int st = 128; st > 0; st >>= 1) {
        if (tid < st) red[tid] = fmaxf(red[tid], red[tid + st]);
        __syncthreads();
    }
    m2 = red[0];
    __syncthreads();
    float sum2 = 0.0f;
#pragma unroll
    for (int l = 0; l < 4; l++) {
        lg[l] = __expf(lg[l] - m2);
        sum2 += lg[l];
    }
    red[tid] = sum2;
    __syncthreads();
    for (int st = 128; st > 0; st >>= 1) {
        if (tid < st) red[tid] += red[tid + st];
        __syncthreads();
    }
    float inv2 = 1.0f / red[0];
#pragma unroll
    for (int l = 0; l < 4; l++) {
        int t = tid + l * 256;
        wr[t] = __float2half(lg[l] * inv2);
    }
}

// ---- K4: out[bh,t,e] = sum_s W[bh,s,t] * Th[b,s,e]   (W^T @ target) ----
// block: 256 threads (8 warps), 128(t) x 64(e) output tile, K(s)-loop in chunks of 64
__global__ void out_gemm(float* __restrict__ out) {
    int bh = blockIdx.z;
    int b = bh / Hc;
    int t0 = blockIdx.x * 128;
    int e0 = blockIdx.y * 64;
    __shared__ __half Ws[64 * 128];  // [s][t]
    __shared__ __half Ts[64 * 64];   // [s][e]
    int tid = threadIdx.x;
    int warp = tid >> 5;
    int r0 = warp * 16;  // t-strip within tile

    wmma::fragment<wmma::accumulator, 16, 16, 16, float> acc[4];
#pragma unroll
    for (int n = 0; n < 4; n++) wmma::fill_fragment(acc[n], 0.0f);

    for (int s0 = 0; s0 < Sc; s0 += 64) {
        const __half* wsrc = g_W + (size_t)bh * Sc * Sc + (size_t)s0 * Sc + t0;
#pragma unroll
        for (int l = 0; l < 4; l++) {
            int o = tid + l * 256;    // 1024 int4 total
            int r = o >> 4, c = o & 15;
            ((int4*)Ws)[r * 16 + c] = ((const int4*)(wsrc + (size_t)r * Sc))[c];
        }
        const __half* tsrc = g_Th + (size_t)b * Sc * Ec + (size_t)s0 * Ec + e0;
#pragma unroll
        for (int l = 0; l < 2; l++) {
            int o = tid + l * 256;    // 512 int4 total
            int r = o >> 3, c = o & 7;
            ((int4*)Ts)[r * 8 + c] = ((const int4*)(tsrc + (size_t)r * Ec))[c];
        }
        __syncthreads();
#pragma unroll
        for (int kk = 0; kk < 4; kk++) {
            // A = W^T : A(t,s) = Ws[s*128 + t], col_major, ldm 128
            wmma::fragment<wmma::matrix_a, 16, 16, 16, __half, wmma::col_major> a;
            wmma::load_matrix_sync(a, Ws + kk * 16 * 128 + r0, 128);
#pragma unroll
            for (int n = 0; n < 4; n++) {
                wmma::fragment<wmma::matrix_b, 16, 16, 16, __half, wmma::row_major> bf;
                wmma::load_matrix_sync(bf, Ts + kk * 16 * 64 + n * 16, 64);
                wmma::mma_sync(acc[n], a, bf, acc[n]);
            }
        }
        __syncthreads();
    }
    float* obase = out + (size_t)bh * Sc * Ec + (size_t)(t0 + r0) * Ec + e0;
#pragma unroll
    for (int n = 0; n < 4; n++)
        wmma::store_matrix_sync(obase + n * 16, acc[n], Ec, wmma::mem_row_major);
}

extern "C" void kernel_launch(void* const* d_in, const int* in_sizes, int n_in,
                              void* d_out, int out_size) {
    (void)in_sizes; (void)n_in; (void)out_size;
    const float* source = (const float*)d_in[0];
    const float* target = (const float*)d_in[1];
    const float* encoder = (const float*)d_in[2];
    const float* alpha = (const float*)d_in[3];
    const float* beta = (const float*)d_in[4];
    const float* gamma = (const float*)d_in[5];
    float* out = (float*)d_out;

    int nconv = Bc * Sc * Ec;
    convert_kernel<<<(nconv + 255) / 256, 256>>>(source, target);
    recurrence_kernel<<<BHc, Dc>>>(target, encoder);
    qk_qc_gemm<<<dim3(Sc / 64, Sc / 64, BHc), 128>>>();
    softmax_kernel<<<BHc * Sc, 256>>>(alpha, beta, gamma);
    out_gemm<<<dim3(Sc / 128, Ec / 64, BHc), 256>>>(out);
}